// round 14
// baseline (speedup 1.0000x reference)
#include <cuda_runtime.h>
#include <cuda_bf16.h>

// Problem constants (fixed by the dataset)
#define Bsz   32768
#define INF   784
#define Hdim  128
#define OUTD  10
#define NSTEP 25

typedef unsigned long long u64;

// -------- packed f32x2 helpers (Blackwell dual-fp32 pipe) --------
__device__ __forceinline__ u64 fma2(u64 a, u64 b, u64 c) {
    u64 d;
    asm("fma.rn.f32x2 %0, %1, %2, %3;" : "=l"(d) : "l"(a), "l"(b), "l"(c));
    return d;
}
__device__ __forceinline__ u64 pack2(float x, float y) {
    u64 d;
    asm("mov.b64 %0, {%1, %2};" : "=l"(d) : "f"(x), "f"(y));
    return d;
}
__device__ __forceinline__ float2 unpack2(u64 a) {
    float2 r;
    asm("mov.b64 {%0, %1}, %2;" : "=f"(r.x), "=f"(r.y) : "l"(a));
    return r;
}

// -------- device scratch (no allocation allowed) --------
__device__ float    g_cur1[(size_t)Bsz * Hdim];        // 16 MB
__device__ unsigned g_spk[(size_t)NSTEP * Bsz * 4];    // 13.1 MB spike bitmasks

// ============================================================
// gemm1: cur1 = x@W1^T + b1. 128x128 tile, BK=16, 256 threads,
// 8x8 microtile, on-the-fly W1 transpose.
// NOW DOUBLE-BUFFERED: one __syncthreads per K-step (was two);
// LDG prefetch + STS into the other buffer overlap with compute.
// Arithmetic identical to the rel_err==0.0 model (single accumulator,
// ascending-k FMA chain, bias added once post-reduction).
// ============================================================
__global__ __launch_bounds__(256, 2) void gemm1_kernel(const float* __restrict__ x,
                                                       const float* __restrict__ W1g,
                                                       const float* __restrict__ b1) {
    __shared__ float2 Asd[2][16][129];   // [buf][k][row] duplicated (a,a)  33.0 KB
    __shared__ float  Bs[2][16][132];    // [buf][k][col], padded           16.9 KB
    __shared__ float  b1s[128];

    const int tid = threadIdx.x;
    const int bm = blockIdx.x * 128;

    if (tid < 128) b1s[tid] = b1[tid];

    const int arow = tid >> 2;          // 0..63
    const int acg  = (tid & 3) * 4;     // k sub-offset 0,4,8,12
    const int sk  = tid & 15;           // k within tile (B transpose map)
    const int sc0 = tid >> 4;           // base col 0..15

    const int tx = tid & 15;            // col group (pairs 2tx+32j)
    const int ty = tid >> 4;            // row group (rows ty*8..ty*8+7)

    u64 cp[8][4];
#pragma unroll
    for (int ri = 0; ri < 8; ri++)
#pragma unroll
        for (int j = 0; j < 4; j++) cp[ri][j] = 0ull;

    // prefetch tile 0 into regs
    float4 a0 = *(const float4*)(x + (size_t)(bm + arow) * INF + acg);
    float4 a1 = *(const float4*)(x + (size_t)(bm + arow + 64) * INF + acg);
    float bpre[8];
#pragma unroll
    for (int p = 0; p < 8; p++)
        bpre[p] = W1g[(size_t)(sc0 + 16 * p) * INF + sk];

    // stage tile 0 into buffer 0
    {
        float2 (*As)[129] = Asd[0];
        float  (*Bb)[132] = Bs[0];
        As[acg + 0][arow] = make_float2(a0.x, a0.x);
        As[acg + 1][arow] = make_float2(a0.y, a0.y);
        As[acg + 2][arow] = make_float2(a0.z, a0.z);
        As[acg + 3][arow] = make_float2(a0.w, a0.w);
        As[acg + 0][arow + 64] = make_float2(a1.x, a1.x);
        As[acg + 1][arow + 64] = make_float2(a1.y, a1.y);
        As[acg + 2][arow + 64] = make_float2(a1.z, a1.z);
        As[acg + 3][arow + 64] = make_float2(a1.w, a1.w);
#pragma unroll
        for (int p = 0; p < 8; p++)
            Bb[sk][sc0 + 16 * p] = bpre[p];
    }
    __syncthreads();

    const int KITER = INF / 16;  // 49
    int cb = 0;
    for (int t = 0; t < KITER; t++) {
        // prefetch tile t+1 into regs (latency hidden by compute below)
        if (t < KITER - 1) {
            int k0 = (t + 1) * 16;
            a0 = *(const float4*)(x + (size_t)(bm + arow) * INF + k0 + acg);
            a1 = *(const float4*)(x + (size_t)(bm + arow + 64) * INF + k0 + acg);
#pragma unroll
            for (int p = 0; p < 8; p++)
                bpre[p] = W1g[(size_t)(sc0 + 16 * p) * INF + k0 + sk];
        }

        // compute on buffer cb
        {
            float2 (*As)[129] = Asd[cb];
            float  (*Bb)[132] = Bs[cb];
#pragma unroll
            for (int kk = 0; kk < 16; kk++) {
                u64 ap[8];
#pragma unroll
                for (int ri = 0; ri < 8; ri++)
                    ap[ri] = *(const u64*)&As[kk][ty * 8 + ri];   // broadcast (a,a)
                u64 bp[4];
#pragma unroll
                for (int j = 0; j < 4; j++)
                    bp[j] = *(const u64*)&Bb[kk][2 * tx + 32 * j]; // contiguous pair
#pragma unroll
                for (int ri = 0; ri < 8; ri++)
#pragma unroll
                    for (int j = 0; j < 4; j++)
                        cp[ri][j] = fma2(ap[ri], bp[j], cp[ri][j]);
            }
        }

        // stage tile t+1 into the other buffer
        if (t < KITER - 1) {
            float2 (*As)[129] = Asd[cb ^ 1];
            float  (*Bb)[132] = Bs[cb ^ 1];
            As[acg + 0][arow] = make_float2(a0.x, a0.x);
            As[acg + 1][arow] = make_float2(a0.y, a0.y);
            As[acg + 2][arow] = make_float2(a0.z, a0.z);
            As[acg + 3][arow] = make_float2(a0.w, a0.w);
            As[acg + 0][arow + 64] = make_float2(a1.x, a1.x);
            As[acg + 1][arow + 64] = make_float2(a1.y, a1.y);
            As[acg + 2][arow + 64] = make_float2(a1.z, a1.z);
            As[acg + 3][arow + 64] = make_float2(a1.w, a1.w);
#pragma unroll
            for (int p = 0; p < 8; p++)
                Bb[sk][sc0 + 16 * p] = bpre[p];
            __syncthreads();
        }
        cb ^= 1;
    }

    // epilogue: add b1 (AFTER the full-K reduction), store float2 pairs
#pragma unroll
    for (int ri = 0; ri < 8; ri++) {
        int r = bm + ty * 8 + ri;
        float* orow = g_cur1 + (size_t)r * Hdim;
#pragma unroll
        for (int j = 0; j < 4; j++) {
            int c = 2 * tx + 32 * j;
            float2 v = unpack2(cp[ri][j]);
            float2 s;
            s.x = __fadd_rn(v.x, b1s[c]);
            s.y = __fadd_rn(v.y, b1s[c + 1]);
            *(float2*)&orow[c] = s;
        }
    }
}

// ============================================================
// lif1: UNCHANGED. Layer-1 LIF, thread = (b,h), membrane in one register,
// spikes emitted as warp ballots (bit i of word w = h = 32w+i).
// ============================================================
__global__ __launch_bounds__(256) void lif1_kernel() {
    const int tid = blockIdx.x * 256 + threadIdx.x;   // = b*128 + h
    const float c = g_cur1[tid];
    const int b = tid >> 7;
    const int word = (tid >> 5) & 3;
    const int lane = threadIdx.x & 31;

    unsigned* dst = g_spk + (size_t)b * 4 + word;
    float m = 0.0f;
#pragma unroll
    for (int t = 0; t < NSTEP; t++) {
        float mo = m;
        m = __fmaf_rn(0.9f, mo, c);
        if (mo > 1.0f) m = __fadd_rn(m, -1.0f);
        unsigned msk = __ballot_sync(0xffffffffu, m > 1.0f);
        if (lane == 0) dst[(size_t)t * Bsz * 4] = msk;
    }
}

// ============================================================
// lif2: layer-2 LIF + tiny GEMM from spike bitmasks.
// Two threads per batch row (parity q -> outputs 5q..5q+4).
// R14 changes:
//  (a) mask for t+1 prefetched into regs during t's compute (kills the
//      dependent ~240-580cyc LDG stall at the top of every step);
//  (b) inner h-body uses setp + 3x predicated add.rn.f32x2 (one asm
//      block) instead of ISETP+2xSEL+3xfma2: @!p is an exact no-op and
//      @p add.rn rounds identically to fma2(1,w,acc) -> chain bitwise
//      unchanged (rel_err stays 0.0). ~7 issue slots/h vs ~10.
// ============================================================
__global__ __launch_bounds__(128) void lif2_kernel(const float* __restrict__ W2g,
                                                   const float* __restrict__ b2g,
                                                   float* __restrict__ out) {
    __shared__ u64 w2q[2][Hdim][4];   // 8 KB: [parity][h][pairs]

    const int tid = threadIdx.x;
    const int q = tid & 1;                    // output-half parity
    const int b = blockIdx.x * 64 + (tid >> 1);

    // one-time w2 repack: i indexes (qq, h)
    for (int i = tid; i < 2 * Hdim; i += 128) {
        int qq = i >> 7;
        int h  = i & 127;
        int o0 = qq * 5;
        w2q[qq][h][0] = pack2(W2g[(o0 + 0) * Hdim + h], W2g[(o0 + 1) * Hdim + h]);
        w2q[qq][h][1] = pack2(W2g[(o0 + 2) * Hdim + h], W2g[(o0 + 3) * Hdim + h]);
        w2q[qq][h][2] = pack2(W2g[(o0 + 4) * Hdim + h], 0.0f);
        w2q[qq][h][3] = 0ull;
    }
    __syncthreads();

    // b2 pairs for this parity (broadcast LDG)
    u64 b2p0 = pack2(b2g[q * 5 + 0], b2g[q * 5 + 1]);
    u64 b2p1 = pack2(b2g[q * 5 + 2], b2g[q * 5 + 3]);
    u64 b2p2 = pack2(b2g[q * 5 + 4], 0.0f);

    float m2a = 0.0f, m2b = 0.0f, m2c = 0.0f, m2d = 0.0f, m2e = 0.0f;

    const unsigned* mbase = g_spk + (size_t)b * 4;
    float* outp = out + (size_t)b * OUTD + q * 5;
    const u64* wbase = &w2q[q][0][0];

    const u64 ONE2 = 0x3F8000003F800000ull;  // packed (1.0f, 1.0f)

    uint4 mk = *(const uint4*)mbase;          // mask for t=0

#pragma unroll 1
    for (int t = 0; t < NSTEP; t++) {
        uint4 nk = mk;
        if (t < NSTEP - 1)                    // prefetch next mask early
            nk = *(const uint4*)(mbase + (size_t)(t + 1) * Bsz * 4);

        u64 a0 = 0ull, a1 = 0ull, a2 = 0ull;

#pragma unroll
        for (int w = 0; w < 4; w++) {
            unsigned mw = (w == 0) ? mk.x : (w == 1) ? mk.y : (w == 2) ? mk.z : mk.w;
            const u64* wp = wbase + (w * 32) * 4;
#pragma unroll 8
            for (int bit = 0; bit < 32; bit++) {
                unsigned tst = mw & (1u << bit);
                u64 w0 = wp[0], w1 = wp[1], w2 = wp[2];
                asm("{\n\t"
                    ".reg .pred p;\n\t"
                    "setp.ne.u32 p, %6, 0;\n\t"
                    "@p add.rn.f32x2 %0, %0, %3;\n\t"
                    "@p add.rn.f32x2 %1, %1, %4;\n\t"
                    "@p add.rn.f32x2 %2, %2, %5;\n\t"
                    "}"
                    : "+l"(a0), "+l"(a1), "+l"(a2)
                    : "l"(w0), "l"(w1), "l"(w2), "r"(tst));
                wp += 4;
            }
        }

        // cu = acc + b2 (element-wise fadd_rn via fma2(1, acc, b2))
        u64 cu0 = fma2(ONE2, a0, b2p0);
        u64 cu1 = fma2(ONE2, a1, b2p1);
        u64 cu2 = fma2(ONE2, a2, b2p2);

        float2 c01 = unpack2(cu0);
        float2 c23 = unpack2(cu1);
        float2 c4x = unpack2(cu2);

        float* op = outp + (size_t)t * Bsz * OUTD;
        {
            float mo = m2a;
            float m = __fmaf_rn(0.9f, mo, c01.x);
            if (mo > 1.0f) m = __fadd_rn(m, -1.0f);
            m2a = m; op[0] = (m > 1.0f) ? 1.0f : 0.0f;
        }
        {
            float mo = m2b;
            float m = __fmaf_rn(0.9f, mo, c01.y);
            if (mo > 1.0f) m = __fadd_rn(m, -1.0f);
            m2b = m; op[1] = (m > 1.0f) ? 1.0f : 0.0f;
        }
        {
            float mo = m2c;
            float m = __fmaf_rn(0.9f, mo, c23.x);
            if (mo > 1.0f) m = __fadd_rn(m, -1.0f);
            m2c = m; op[2] = (m > 1.0f) ? 1.0f : 0.0f;
        }
        {
            float mo = m2d;
            float m = __fmaf_rn(0.9f, mo, c23.y);
            if (mo > 1.0f) m = __fadd_rn(m, -1.0f);
            m2d = m; op[3] = (m > 1.0f) ? 1.0f : 0.0f;
        }
        {
            float mo = m2e;
            float m = __fmaf_rn(0.9f, mo, c4x.x);
            if (mo > 1.0f) m = __fadd_rn(m, -1.0f);
            m2e = m; op[4] = (m > 1.0f) ? 1.0f : 0.0f;
        }

        mk = nk;
    }
}

// ============================================================
extern "C" void kernel_launch(void* const* d_in, const int* in_sizes, int n_in,
                              void* d_out, int out_size) {
    (void)in_sizes; (void)n_in; (void)out_size;
    const float* x  = (const float*)d_in[0];
    const float* W1 = (const float*)d_in[1];
    const float* b1 = (const float*)d_in[2];
    const float* W2 = (const float*)d_in[3];
    const float* b2 = (const float*)d_in[4];
    float* out = (float*)d_out;

    gemm1_kernel<<<Bsz / 128, 256>>>(x, W1, b1);
    lif1_kernel<<<(Bsz * Hdim) / 256, 256>>>();
    lif2_kernel<<<Bsz / 64, 128>>>(W2, b2, out);
}

// round 15
// speedup vs baseline: 1.0077x; 1.0077x over previous
#include <cuda_runtime.h>
#include <cuda_bf16.h>

// Problem constants (fixed by the dataset)
#define Bsz   32768
#define INF   784
#define Hdim  128
#define OUTD  10
#define NSTEP 25

typedef unsigned long long u64;

// -------- packed f32x2 helpers (Blackwell dual-fp32 pipe) --------
__device__ __forceinline__ u64 fma2(u64 a, u64 b, u64 c) {
    u64 d;
    asm("fma.rn.f32x2 %0, %1, %2, %3;" : "=l"(d) : "l"(a), "l"(b), "l"(c));
    return d;
}
__device__ __forceinline__ u64 pack2(float x, float y) {
    u64 d;
    asm("mov.b64 %0, {%1, %2};" : "=l"(d) : "f"(x), "f"(y));
    return d;
}
__device__ __forceinline__ float2 unpack2(u64 a) {
    float2 r;
    asm("mov.b64 {%0, %1}, %2;" : "=f"(r.x), "=f"(r.y) : "l"(a));
    return r;
}

// -------- device scratch (no allocation allowed) --------
__device__ float    g_cur1[(size_t)Bsz * Hdim];              // 16 MB
__device__ unsigned g_spk[(size_t)NSTEP * Bsz * 4];          // 13.1 MB spike bitmasks
__device__ u64      g_cur2[(size_t)NSTEP * Bsz * 2 * 3];     // 39.3 MB cur2 (packed pairs)

// ============================================================
// gemm1: cur1 = x@W1^T + b1. 128x128 tile, BK=16, 256 threads,
// 8x8 microtile, on-the-fly W1 transpose, double-buffered.
// R15: 128-bit shared loads — A rows paired (pad 130 -> rows 16B-aligned,
// 4x LDS.128) and contiguous column quads {4tx..4tx+3, +64} (2x LDS.128).
// LDS instr per kk: 12 -> 6 (crossbar-issue pressure halved).
// Per-element reduction order UNCHANGED (single accumulator, ascending-k
// chain; bias added once post-reduction) -> bitwise rel_err 0.0 model.
// ============================================================
__global__ __launch_bounds__(256, 2) void gemm1_kernel(const float* __restrict__ x,
                                                       const float* __restrict__ W1g,
                                                       const float* __restrict__ b1) {
    __shared__ __align__(16) float2 Asd[2][16][130];   // [buf][k][row] (a,a); row=1040B, 16B-aligned
    __shared__ __align__(16) float  Bs[2][16][132];    // [buf][k][col]; row=528B, 16B-aligned
    __shared__ float  b1s[128];

    const int tid = threadIdx.x;
    const int bm = blockIdx.x * 128;

    if (tid < 128) b1s[tid] = b1[tid];

    const int arow = tid >> 2;          // 0..63
    const int acg  = (tid & 3) * 4;     // k sub-offset 0,4,8,12
    const int sk  = tid & 15;           // k within tile (B transpose map)
    const int sc0 = tid >> 4;           // base col 0..15

    const int tx = tid & 15;            // col group (quads 4tx+64jj)
    const int ty = tid >> 4;            // row group (rows ty*8..ty*8+7)

    // accumulators: 8 rows x 4 col-pairs; cp[rr][2jj+e] = cols (4tx+64jj+2e, +1)
    u64 cp[8][4];
#pragma unroll
    for (int rr = 0; rr < 8; rr++)
#pragma unroll
        for (int j = 0; j < 4; j++) cp[rr][j] = 0ull;

    // prefetch tile 0 into regs
    float4 a0 = *(const float4*)(x + (size_t)(bm + arow) * INF + acg);
    float4 a1 = *(const float4*)(x + (size_t)(bm + arow + 64) * INF + acg);
    float bpre[8];
#pragma unroll
    for (int p = 0; p < 8; p++)
        bpre[p] = W1g[(size_t)(sc0 + 16 * p) * INF + sk];

    // stage tile 0 into buffer 0
    {
        float2 (*As)[130] = Asd[0];
        float  (*Bb)[132] = Bs[0];
        As[acg + 0][arow] = make_float2(a0.x, a0.x);
        As[acg + 1][arow] = make_float2(a0.y, a0.y);
        As[acg + 2][arow] = make_float2(a0.z, a0.z);
        As[acg + 3][arow] = make_float2(a0.w, a0.w);
        As[acg + 0][arow + 64] = make_float2(a1.x, a1.x);
        As[acg + 1][arow + 64] = make_float2(a1.y, a1.y);
        As[acg + 2][arow + 64] = make_float2(a1.z, a1.z);
        As[acg + 3][arow + 64] = make_float2(a1.w, a1.w);
#pragma unroll
        for (int p = 0; p < 8; p++)
            Bb[sk][sc0 + 16 * p] = bpre[p];
    }
    __syncthreads();

    const int KITER = INF / 16;  // 49
    int cb = 0;
    for (int t = 0; t < KITER; t++) {
        // prefetch tile t+1 into regs (hidden under compute)
        if (t < KITER - 1) {
            int k0 = (t + 1) * 16;
            a0 = *(const float4*)(x + (size_t)(bm + arow) * INF + k0 + acg);
            a1 = *(const float4*)(x + (size_t)(bm + arow + 64) * INF + k0 + acg);
#pragma unroll
            for (int p = 0; p < 8; p++)
                bpre[p] = W1g[(size_t)(sc0 + 16 * p) * INF + k0 + sk];
        }

        // compute on buffer cb: per kk = 6 LDS.128 + 32 FFMA2
        {
            float2 (*As)[130] = Asd[cb];
            float  (*Bb)[132] = Bs[cb];
#pragma unroll
            for (int kk = 0; kk < 16; kk++) {
                float4 bv0 = *(const float4*)&Bb[kk][4 * tx];
                float4 bv1 = *(const float4*)&Bb[kk][4 * tx + 64];
                u64 b00 = ((const u64*)&bv0)[0], b01 = ((const u64*)&bv0)[1];
                u64 b10 = ((const u64*)&bv1)[0], b11 = ((const u64*)&bv1)[1];
#pragma unroll
                for (int p = 0; p < 4; p++) {
                    float4 av = *(const float4*)&As[kk][ty * 8 + 2 * p]; // rows 2p,2p+1 dup'd
                    u64 alo = ((const u64*)&av)[0];
                    u64 ahi = ((const u64*)&av)[1];
                    cp[2*p  ][0] = fma2(alo, b00, cp[2*p  ][0]);
                    cp[2*p  ][1] = fma2(alo, b01, cp[2*p  ][1]);
                    cp[2*p  ][2] = fma2(alo, b10, cp[2*p  ][2]);
                    cp[2*p  ][3] = fma2(alo, b11, cp[2*p  ][3]);
                    cp[2*p+1][0] = fma2(ahi, b00, cp[2*p+1][0]);
                    cp[2*p+1][1] = fma2(ahi, b01, cp[2*p+1][1]);
                    cp[2*p+1][2] = fma2(ahi, b10, cp[2*p+1][2]);
                    cp[2*p+1][3] = fma2(ahi, b11, cp[2*p+1][3]);
                }
            }
        }

        // stage tile t+1 into the other buffer
        if (t < KITER - 1) {
            float2 (*As)[130] = Asd[cb ^ 1];
            float  (*Bb)[132] = Bs[cb ^ 1];
            As[acg + 0][arow] = make_float2(a0.x, a0.x);
            As[acg + 1][arow] = make_float2(a0.y, a0.y);
            As[acg + 2][arow] = make_float2(a0.z, a0.z);
            As[acg + 3][arow] = make_float2(a0.w, a0.w);
            As[acg + 0][arow + 64] = make_float2(a1.x, a1.x);
            As[acg + 1][arow + 64] = make_float2(a1.y, a1.y);
            As[acg + 2][arow + 64] = make_float2(a1.z, a1.z);
            As[acg + 3][arow + 64] = make_float2(a1.w, a1.w);
#pragma unroll
            for (int p = 0; p < 8; p++)
                Bb[sk][sc0 + 16 * p] = bpre[p];
            __syncthreads();
        }
        cb ^= 1;
    }

    // epilogue: add b1 (AFTER full-K reduction), STG.128 per column quad
#pragma unroll
    for (int rr = 0; rr < 8; rr++) {
        int r = bm + ty * 8 + rr;
        float* orow = g_cur1 + (size_t)r * Hdim;
#pragma unroll
        for (int jj = 0; jj < 2; jj++) {
            int c = 4 * tx + 64 * jj;
            float2 v0 = unpack2(cp[rr][2 * jj]);
            float2 v1 = unpack2(cp[rr][2 * jj + 1]);
            float4 s;
            s.x = __fadd_rn(v0.x, b1s[c + 0]);
            s.y = __fadd_rn(v0.y, b1s[c + 1]);
            s.z = __fadd_rn(v1.x, b1s[c + 2]);
            s.w = __fadd_rn(v1.y, b1s[c + 3]);
            *(float4*)&orow[c] = s;
        }
    }
}

// ============================================================
// lif1: UNCHANGED. Layer-1 LIF, thread = (b,h), membrane in one register,
// spikes emitted as warp ballots (bit i of word w = h = 32w+i).
// ============================================================
__global__ __launch_bounds__(256) void lif1_kernel() {
    const int tid = blockIdx.x * 256 + threadIdx.x;   // = b*128 + h
    const float c = g_cur1[tid];
    const int b = tid >> 7;
    const int word = (tid >> 5) & 3;
    const int lane = threadIdx.x & 31;

    unsigned* dst = g_spk + (size_t)b * 4 + word;
    float m = 0.0f;
#pragma unroll
    for (int t = 0; t < NSTEP; t++) {
        float mo = m;
        m = __fmaf_rn(0.9f, mo, c);
        if (mo > 1.0f) m = __fadd_rn(m, -1.0f);
        unsigned msk = __ballot_sync(0xffffffffu, m > 1.0f);
        if (lane == 0) dst[(size_t)t * Bsz * 4] = msk;
    }
}

// ============================================================
// cur2: cur2[t,b] = spikes(t,b) @ W2^T + b2 — fully parallel over (t,b,q)
// (the 25-step recurrence only couples through the 5 m2 scalars, handled
// by scan_kernel). 1.64M threads -> occupancy ceiling of the old lif2
// (grid-limited 3.46 warps/SMSP) is gone.
// Accumulation chain bitwise identical: ascending-h predicated add.rn.f32x2
// (@!p exact no-op, @p add.rn == fma2(1,w,acc)); +b2 post-reduction.
// ============================================================
__global__ __launch_bounds__(256) void cur2_kernel(const float* __restrict__ W2g,
                                                   const float* __restrict__ b2g) {
    __shared__ u64 w2q[2][Hdim][4];   // 8 KB: [parity][h][pairs]

    const int tid = threadIdx.x;
    // repack: exactly 256 entries = 256 threads
    {
        int qq = tid >> 7;
        int h  = tid & 127;
        int o0 = qq * 5;
        w2q[qq][h][0] = pack2(W2g[(o0 + 0) * Hdim + h], W2g[(o0 + 1) * Hdim + h]);
        w2q[qq][h][1] = pack2(W2g[(o0 + 2) * Hdim + h], W2g[(o0 + 3) * Hdim + h]);
        w2q[qq][h][2] = pack2(W2g[(o0 + 4) * Hdim + h], 0.0f);
        w2q[qq][h][3] = 0ull;
    }
    __syncthreads();

    const int gid = blockIdx.x * 256 + tid;      // = ((t*Bsz + b)*2 + q)
    const int q  = gid & 1;
    const size_t tb = (size_t)(gid >> 1);        // t*Bsz + b

    uint4 mk = *(const uint4*)(g_spk + tb * 4);

    u64 b2p0 = pack2(b2g[q * 5 + 0], b2g[q * 5 + 1]);
    u64 b2p1 = pack2(b2g[q * 5 + 2], b2g[q * 5 + 3]);
    u64 b2p2 = pack2(b2g[q * 5 + 4], 0.0f);

    const u64* wbase = &w2q[q][0][0];
    u64 a0 = 0ull, a1 = 0ull, a2 = 0ull;

#pragma unroll
    for (int w = 0; w < 4; w++) {
        unsigned mw = (w == 0) ? mk.x : (w == 1) ? mk.y : (w == 2) ? mk.z : mk.w;
        const u64* wp = wbase + (w * 32) * 4;
#pragma unroll 8
        for (int bit = 0; bit < 32; bit++) {
            unsigned tst = mw & (1u << bit);
            u64 w0 = wp[0], w1 = wp[1], w2 = wp[2];
            asm("{\n\t"
                ".reg .pred p;\n\t"
                "setp.ne.u32 p, %6, 0;\n\t"
                "@p add.rn.f32x2 %0, %0, %3;\n\t"
                "@p add.rn.f32x2 %1, %1, %4;\n\t"
                "@p add.rn.f32x2 %2, %2, %5;\n\t"
                "}"
                : "+l"(a0), "+l"(a1), "+l"(a2)
                : "l"(w0), "l"(w1), "l"(w2), "r"(tst));
            wp += 4;
        }
    }

    // +b2 after the full reduction (element-wise fadd_rn via fma2(1,acc,b2))
    const u64 ONE2 = 0x3F8000003F800000ull;
    u64* dst = g_cur2 + (size_t)gid * 3;
    dst[0] = fma2(ONE2, a0, b2p0);
    dst[1] = fma2(ONE2, a1, b2p1);
    dst[2] = fma2(ONE2, a2, b2p2);
}

// ============================================================
// scan: 25-step layer-2 LIF over precomputed cur2. Thread = (b,q);
// next-step cur2 prefetched into regs; 5 scalar LIF updates per step
// (exact FFMA + predicated-subtract model -> bitwise unchanged).
// ============================================================
__global__ __launch_bounds__(128) void scan_kernel(float* __restrict__ out) {
    const int sid = blockIdx.x * 128 + threadIdx.x;   // = b*2 + q
    const int q = sid & 1;
    const int b = sid >> 1;

    float m2a = 0.0f, m2b = 0.0f, m2c = 0.0f, m2d = 0.0f, m2e = 0.0f;
    float* outp = out + (size_t)b * OUTD + q * 5;

    const u64* src0 = g_cur2 + (size_t)sid * 3;       // t=0 slot for this (b,q)
    u64 c0 = src0[0], c1 = src0[1], c2 = src0[2];

#pragma unroll 1
    for (int t = 0; t < NSTEP; t++) {
        u64 n0 = c0, n1 = c1, n2 = c2;
        if (t < NSTEP - 1) {
            const u64* srcn = g_cur2 + ((size_t)(t + 1) * Bsz * 2 + sid) * 3;
            n0 = srcn[0]; n1 = srcn[1]; n2 = srcn[2];
        }

        float2 c01 = unpack2(c0);
        float2 c23 = unpack2(c1);
        float2 c4x = unpack2(c2);

        float* op = outp + (size_t)t * Bsz * OUTD;
        {
            float mo = m2a;
            float m = __fmaf_rn(0.9f, mo, c01.x);
            if (mo > 1.0f) m = __fadd_rn(m, -1.0f);
            m2a = m; op[0] = (m > 1.0f) ? 1.0f : 0.0f;
        }
        {
            float mo = m2b;
            float m = __fmaf_rn(0.9f, mo, c01.y);
            if (mo > 1.0f) m = __fadd_rn(m, -1.0f);
            m2b = m; op[1] = (m > 1.0f) ? 1.0f : 0.0f;
        }
        {
            float mo = m2c;
            float m = __fmaf_rn(0.9f, mo, c23.x);
            if (mo > 1.0f) m = __fadd_rn(m, -1.0f);
            m2c = m; op[2] = (m > 1.0f) ? 1.0f : 0.0f;
        }
        {
            float mo = m2d;
            float m = __fmaf_rn(0.9f, mo, c23.y);
            if (mo > 1.0f) m = __fadd_rn(m, -1.0f);
            m2d = m; op[3] = (m > 1.0f) ? 1.0f : 0.0f;
        }
        {
            float mo = m2e;
            float m = __fmaf_rn(0.9f, mo, c4x.x);
            if (mo > 1.0f) m = __fadd_rn(m, -1.0f);
            m2e = m; op[4] = (m > 1.0f) ? 1.0f : 0.0f;
        }

        c0 = n0; c1 = n1; c2 = n2;
    }
}

// ============================================================
extern "C" void kernel_launch(void* const* d_in, const int* in_sizes, int n_in,
                              void* d_out, int out_size) {
    (void)in_sizes; (void)n_in; (void)out_size;
    const float* x  = (const float*)d_in[0];
    const float* W1 = (const float*)d_in[1];
    const float* b1 = (const float*)d_in[2];
    const float* W2 = (const float*)d_in[3];
    const float* b2 = (const float*)d_in[4];
    float* out = (float*)d_out;

    gemm1_kernel<<<Bsz / 128, 256>>>(x, W1, b1);
    lif1_kernel<<<(Bsz * Hdim) / 256, 256>>>();
    cur2_kernel<<<(NSTEP * Bsz * 2) / 256, 256>>>(W2, b2);
    scan_kernel<<<(Bsz * 2) / 128, 128>>>(out);
}